// round 1
// baseline (speedup 1.0000x reference)
#include <cuda_runtime.h>
#include <cstdint>

#define NUM_HEADS 16
#define SEQ 2048
#define HDIM 64
#define HID 1024
#define BATCH 2
#define M_TOTAL (BATCH * SEQ)      // 4096
#define BH (BATCH * NUM_HEADS)     // 32
#define SCALE 0.125f               // 1/sqrt(64)

// Scratch (no cudaMalloc allowed): 96 MB total
__device__ float g_QP [(size_t)BH * SEQ * 128];   // [b,h,s, 0:64]=Q, [64:128]=P
__device__ float g_KPK[(size_t)BH * SEQ * 128];   // [b,h,s, 0:64]=K+P, [64:128]=K
__device__ float g_V  [(size_t)BH * SEQ * HDIM];  // [b,h,s,d]
__device__ float g_O  [(size_t)M_TOTAL * HID];    // [b,s,h*64+d]

// ---------------------------------------------------------------------------
// NT GEMM with bias: C[m,n] = sum_k X[m,k]*W[n,k] + bias[n]
// M=4096, N=1024, K=1024. BM=BN=128, BK=16. 256 threads, 8x8 per thread.
// mode 0: dst[m*HID + n]                          (final output)
// mode 1: dst[((b*16+h)*SEQ+s)*128 + off + d]     (QP / KPK head layout)
// mode 2: dst[((b*16+h)*SEQ+s)*64 + d]            (V head layout)
// ---------------------------------------------------------------------------
__global__ __launch_bounds__(256) void gemm_proj(
    const float* __restrict__ X, const float* __restrict__ W,
    const float* __restrict__ bias, float* __restrict__ dst,
    int mode, int off)
{
    __shared__ float As[16][128];
    __shared__ float Bs[16][128];
    const int tid = threadIdx.x;
    const int tx = tid & 15, ty = tid >> 4;
    const int m0 = blockIdx.y * 128, n0 = blockIdx.x * 128;

    float acc[8][8];
#pragma unroll
    for (int i = 0; i < 8; i++)
#pragma unroll
        for (int j = 0; j < 8; j++) acc[i][j] = 0.f;

    for (int kt = 0; kt < 1024; kt += 16) {
#pragma unroll
        for (int l = 0; l < 2; l++) {
            int lin = tid + l * 256;             // [0,512)
            int row = lin >> 2, c4 = lin & 3;
            float4 a = *(const float4*)(X + (size_t)(m0 + row) * 1024 + kt + c4 * 4);
            As[c4 * 4 + 0][row] = a.x; As[c4 * 4 + 1][row] = a.y;
            As[c4 * 4 + 2][row] = a.z; As[c4 * 4 + 3][row] = a.w;
            float4 b = *(const float4*)(W + (size_t)(n0 + row) * 1024 + kt + c4 * 4);
            Bs[c4 * 4 + 0][row] = b.x; Bs[c4 * 4 + 1][row] = b.y;
            Bs[c4 * 4 + 2][row] = b.z; Bs[c4 * 4 + 3][row] = b.w;
        }
        __syncthreads();
#pragma unroll
        for (int k = 0; k < 16; k++) {
            float a[8], b[8];
#pragma unroll
            for (int i = 0; i < 8; i++) a[i] = As[k][ty * 8 + i];
#pragma unroll
            for (int j = 0; j < 8; j++) b[j] = Bs[k][tx * 8 + j];
#pragma unroll
            for (int i = 0; i < 8; i++)
#pragma unroll
                for (int j = 0; j < 8; j++) acc[i][j] += a[i] * b[j];
        }
        __syncthreads();
    }

#pragma unroll
    for (int i = 0; i < 8; i++) {
        int m = m0 + ty * 8 + i;
#pragma unroll
        for (int j = 0; j < 8; j++) {
            int n = n0 + tx * 8 + j;
            float v = acc[i][j] + bias[n];
            if (mode == 0) {
                dst[(size_t)m * HID + n] = v;
            } else {
                int b = m >> 11, s = m & 2047;
                int h = n >> 6, d = n & 63;
                if (mode == 1)
                    dst[(((size_t)(b * NUM_HEADS + h) * SEQ + s) * 128) + off + d] = v;
                else
                    dst[(((size_t)(b * NUM_HEADS + h) * SEQ + s) * 64) + d] = v;
            }
        }
    }
}

// KPK[...,0:64] = K (stored at 64:) + P (stored in QP at 64:)
__global__ __launch_bounds__(256) void kp_add()
{
    size_t i = (size_t)blockIdx.x * 256 + threadIdx.x;  // over BH*SEQ*64
    size_t r = i >> 6, d = i & 63;
    g_KPK[r * 128 + d] = g_KPK[r * 128 + 64 + d] + g_QP[r * 128 + 64 + d];
}

// ---------------------------------------------------------------------------
// Scores: per (b,h), S[q,k] = (QP[q,:] . KPK[k,:]) * SCALE + mask[q,k]
// 2048x2048, K=128. Same 128x128x16 tiling. Writes raw (pre-softmax) scores.
// ---------------------------------------------------------------------------
__global__ __launch_bounds__(256) void gemm_scores(
    const float* __restrict__ mask, float* __restrict__ weights)
{
    const int bh = blockIdx.z;
    const float* A = g_QP  + (size_t)bh * SEQ * 128;
    const float* B = g_KPK + (size_t)bh * SEQ * 128;
    float* C = weights + (size_t)bh * SEQ * SEQ;

    __shared__ float As[16][128];
    __shared__ float Bs[16][128];
    const int tid = threadIdx.x;
    const int tx = tid & 15, ty = tid >> 4;
    const int m0 = blockIdx.y * 128, n0 = blockIdx.x * 128;

    float acc[8][8];
#pragma unroll
    for (int i = 0; i < 8; i++)
#pragma unroll
        for (int j = 0; j < 8; j++) acc[i][j] = 0.f;

    for (int kt = 0; kt < 128; kt += 16) {
#pragma unroll
        for (int l = 0; l < 2; l++) {
            int lin = tid + l * 256;
            int row = lin >> 2, c4 = lin & 3;
            float4 a = *(const float4*)(A + (size_t)(m0 + row) * 128 + kt + c4 * 4);
            As[c4 * 4 + 0][row] = a.x; As[c4 * 4 + 1][row] = a.y;
            As[c4 * 4 + 2][row] = a.z; As[c4 * 4 + 3][row] = a.w;
            float4 b = *(const float4*)(B + (size_t)(n0 + row) * 128 + kt + c4 * 4);
            Bs[c4 * 4 + 0][row] = b.x; Bs[c4 * 4 + 1][row] = b.y;
            Bs[c4 * 4 + 2][row] = b.z; Bs[c4 * 4 + 3][row] = b.w;
        }
        __syncthreads();
#pragma unroll
        for (int k = 0; k < 16; k++) {
            float a[8], b[8];
#pragma unroll
            for (int i = 0; i < 8; i++) a[i] = As[k][ty * 8 + i];
#pragma unroll
            for (int j = 0; j < 8; j++) b[j] = Bs[k][tx * 8 + j];
#pragma unroll
            for (int i = 0; i < 8; i++)
#pragma unroll
                for (int j = 0; j < 8; j++) acc[i][j] += a[i] * b[j];
        }
        __syncthreads();
    }

#pragma unroll
    for (int i = 0; i < 8; i++) {
        int q = m0 + ty * 8 + i;
#pragma unroll
        for (int j = 0; j < 8; j++) {
            int k = n0 + tx * 8 + j;
            C[(size_t)q * SEQ + k] = acc[i][j] * SCALE + mask[(size_t)q * SEQ + k];
        }
    }
}

// In-place row softmax over 2048 cols. One block (256 thr) per row.
__global__ __launch_bounds__(256) void softmax_rows(float* __restrict__ w)
{
    __shared__ float red[256];
    const size_t row = blockIdx.x;
    float* p = w + row * (size_t)SEQ;
    const int tid = threadIdx.x;

    float v[8];
    float mx = -1e30f;
#pragma unroll
    for (int i = 0; i < 8; i++) {
        v[i] = p[tid + i * 256];
        mx = fmaxf(mx, v[i]);
    }
    red[tid] = mx;
    __syncthreads();
    for (int s = 128; s > 0; s >>= 1) {
        if (tid < s) red[tid] = fmaxf(red[tid], red[tid + s]);
        __syncthreads();
    }
    mx = red[0];
    __syncthreads();

    float sum = 0.f;
#pragma unroll
    for (int i = 0; i < 8; i++) {
        v[i] = __expf(v[i] - mx);
        sum += v[i];
    }
    red[tid] = sum;
    __syncthreads();
    for (int s = 128; s > 0; s >>= 1) {
        if (tid < s) red[tid] += red[tid + s];
        __syncthreads();
    }
    float inv = 1.f / red[0];
#pragma unroll
    for (int i = 0; i < 8; i++) p[tid + i * 256] = v[i] * inv;
}

// ---------------------------------------------------------------------------
// AV: per (b,h), O[q,d] = sum_k W[q,k]*V[k,d].  M=2048, N=64, K=2048.
// BM=128, BN=64, BK=32. 256 threads, 8x4 per thread. O stored [b,s,h*64+d].
// ---------------------------------------------------------------------------
__global__ __launch_bounds__(256) void gemm_av(const float* __restrict__ weights)
{
    const int bh = blockIdx.y;
    const int b = bh >> 4, h = bh & 15;
    const float* Wm = weights + (size_t)bh * SEQ * SEQ;
    const float* V  = g_V + (size_t)bh * SEQ * HDIM;

    __shared__ float Ws[32][128];
    __shared__ float Vs[32][64];
    const int tid = threadIdx.x;
    const int tx = tid & 15, ty = tid >> 4;
    const int m0 = blockIdx.x * 128;

    float acc[8][4];
#pragma unroll
    for (int i = 0; i < 8; i++)
#pragma unroll
        for (int j = 0; j < 4; j++) acc[i][j] = 0.f;

    for (int kt = 0; kt < SEQ; kt += 32) {
#pragma unroll
        for (int l = 0; l < 4; l++) {
            int lin = tid + l * 256;             // [0,1024)
            int row = lin >> 3, c4 = lin & 7;
            float4 a = *(const float4*)(Wm + (size_t)(m0 + row) * SEQ + kt + c4 * 4);
            Ws[c4 * 4 + 0][row] = a.x; Ws[c4 * 4 + 1][row] = a.y;
            Ws[c4 * 4 + 2][row] = a.z; Ws[c4 * 4 + 3][row] = a.w;
        }
#pragma unroll
        for (int l = 0; l < 2; l++) {
            int lin = tid + l * 256;             // [0,512)
            int row = lin >> 4, c4 = lin & 15;
            *(float4*)&Vs[row][c4 * 4] =
                *(const float4*)(V + (size_t)(kt + row) * HDIM + c4 * 4);
        }
        __syncthreads();
#pragma unroll
        for (int k = 0; k < 32; k++) {
            float a[8], bb[4];
#pragma unroll
            for (int i = 0; i < 8; i++) a[i] = Ws[k][ty * 8 + i];
#pragma unroll
            for (int j = 0; j < 4; j++) bb[j] = Vs[k][tx * 4 + j];
#pragma unroll
            for (int i = 0; i < 8; i++)
#pragma unroll
                for (int j = 0; j < 4; j++) acc[i][j] += a[i] * bb[j];
        }
        __syncthreads();
    }

#pragma unroll
    for (int i = 0; i < 8; i++) {
        int s = m0 + ty * 8 + i;
#pragma unroll
        for (int j = 0; j < 4; j++) {
            int d = tx * 4 + j;
            g_O[(size_t)b * SEQ * HID + (size_t)s * HID + h * 64 + d] = acc[i][j];
        }
    }
}

// ---------------------------------------------------------------------------
extern "C" void kernel_launch(void* const* d_in, const int* in_sizes, int n_in,
                              void* d_out, int out_size)
{
    const float* q    = (const float*)d_in[0];
    const float* k    = (const float*)d_in[1];
    const float* v    = (const float*)d_in[2];
    const float* pos  = (const float*)d_in[3];
    const float* mask = (const float*)d_in[4];
    const float* Wq = (const float*)d_in[5];  const float* bq = (const float*)d_in[6];
    const float* Wk = (const float*)d_in[7];  const float* bk = (const float*)d_in[8];
    const float* Wv = (const float*)d_in[9];  const float* bv = (const float*)d_in[10];
    const float* Wp = (const float*)d_in[11]; const float* bp = (const float*)d_in[12];
    const float* Wo = (const float*)d_in[13]; const float* bo = (const float*)d_in[14];

    float* out = (float*)d_out;
    float* weights = out + (size_t)BATCH * SEQ * HID;   // out first, then weights

    float *QP, *KPK, *Vd, *O;
    cudaGetSymbolAddress((void**)&QP,  g_QP);
    cudaGetSymbolAddress((void**)&KPK, g_KPK);
    cudaGetSymbolAddress((void**)&Vd,  g_V);
    cudaGetSymbolAddress((void**)&O,   g_O);

    dim3 blk(256);
    dim3 gproj(HID / 128, M_TOTAL / 128);   // (8, 32)

    gemm_proj<<<gproj, blk>>>(q,   Wq, bq, QP,  1, 0);   // Q  -> QP[:,0:64]
    gemm_proj<<<gproj, blk>>>(pos, Wp, bp, QP,  1, 64);  // P  -> QP[:,64:128]
    gemm_proj<<<gproj, blk>>>(k,   Wk, bk, KPK, 1, 64);  // K  -> KPK[:,64:128]
    gemm_proj<<<gproj, blk>>>(v,   Wv, bv, Vd,  2, 0);   // V

    kp_add<<<(BH * SEQ * 64) / 256, blk>>>();            // KPK[:,0:64] = K + P

    dim3 gsc(SEQ / 128, SEQ / 128, BH);                  // (16,16,32)
    gemm_scores<<<gsc, blk>>>(mask, weights);

    softmax_rows<<<BH * SEQ, blk>>>(weights);

    gemm_av<<<dim3(SEQ / 128, BH), blk>>>(weights);

    gemm_proj<<<gproj, blk>>>(O, Wo, bo, out, 0, 0);     // final projection
}

// round 2
// speedup vs baseline: 1.0005x; 1.0005x over previous
#include <cuda_runtime.h>
#include <cstdint>

#define NUM_HEADS 16
#define SEQ 2048
#define HDIM 64
#define HID 1024
#define BATCH 2
#define M_TOTAL (BATCH * SEQ)      // 4096
#define BH (BATCH * NUM_HEADS)     // 32
#define SCALE 0.125f               // 1/sqrt(64)

// Scratch (no cudaMalloc allowed): 96 MB total
__device__ float g_QP [(size_t)BH * SEQ * 128];   // [b,h,s, 0:64]=Q, [64:128]=P
__device__ float g_KPK[(size_t)BH * SEQ * 128];   // [b,h,s, 0:64]=K+P, [64:128]=K
__device__ float g_V  [(size_t)BH * SEQ * HDIM];  // [b,h,s,d]
__device__ float g_O  [(size_t)M_TOTAL * HID];    // [b,s,h*64+d]

// ---------------------------------------------------------------------------
// NT GEMM with bias: C[m,n] = sum_k X[m,k]*W[n,k] + bias[n]
// M=4096, N=1024, K=1024. BM=BN=128, BK=16. 256 threads, 8x8 per thread.
// mode 0: dst[m*HID + n]                          (final output)
// mode 1: dst[((b*16+h)*SEQ+s)*128 + off + d]     (QP / KPK head layout)
// mode 2: dst[((b*16+h)*SEQ+s)*64 + d]            (V head layout)
// ---------------------------------------------------------------------------
__global__ __launch_bounds__(256) void gemm_proj(
    const float* __restrict__ X, const float* __restrict__ W,
    const float* __restrict__ bias, float* __restrict__ dst,
    int mode, int off)
{
    __shared__ float As[16][128];
    __shared__ float Bs[16][128];
    const int tid = threadIdx.x;
    const int tx = tid & 15, ty = tid >> 4;
    const int m0 = blockIdx.y * 128, n0 = blockIdx.x * 128;

    float acc[8][8];
#pragma unroll
    for (int i = 0; i < 8; i++)
#pragma unroll
        for (int j = 0; j < 8; j++) acc[i][j] = 0.f;

    for (int kt = 0; kt < 1024; kt += 16) {
#pragma unroll
        for (int l = 0; l < 2; l++) {
            int lin = tid + l * 256;             // [0,512)
            int row = lin >> 2, c4 = lin & 3;
            float4 a = *(const float4*)(X + (size_t)(m0 + row) * 1024 + kt + c4 * 4);
            As[c4 * 4 + 0][row] = a.x; As[c4 * 4 + 1][row] = a.y;
            As[c4 * 4 + 2][row] = a.z; As[c4 * 4 + 3][row] = a.w;
            float4 b = *(const float4*)(W + (size_t)(n0 + row) * 1024 + kt + c4 * 4);
            Bs[c4 * 4 + 0][row] = b.x; Bs[c4 * 4 + 1][row] = b.y;
            Bs[c4 * 4 + 2][row] = b.z; Bs[c4 * 4 + 3][row] = b.w;
        }
        __syncthreads();
#pragma unroll
        for (int k = 0; k < 16; k++) {
            float a[8], b[8];
#pragma unroll
            for (int i = 0; i < 8; i++) a[i] = As[k][ty * 8 + i];
#pragma unroll
            for (int j = 0; j < 8; j++) b[j] = Bs[k][tx * 8 + j];
#pragma unroll
            for (int i = 0; i < 8; i++)
#pragma unroll
                for (int j = 0; j < 8; j++) acc[i][j] += a[i] * b[j];
        }
        __syncthreads();
    }

#pragma unroll
    for (int i = 0; i < 8; i++) {
        int m = m0 + ty * 8 + i;
#pragma unroll
        for (int j = 0; j < 8; j++) {
            int n = n0 + tx * 8 + j;
            float v = acc[i][j] + bias[n];
            if (mode == 0) {
                dst[(size_t)m * HID + n] = v;
            } else {
                int b = m >> 11, s = m & 2047;
                int h = n >> 6, d = n & 63;
                if (mode == 1)
                    dst[(((size_t)(b * NUM_HEADS + h) * SEQ + s) * 128) + off + d] = v;
                else
                    dst[(((size_t)(b * NUM_HEADS + h) * SEQ + s) * 64) + d] = v;
            }
        }
    }
}

// KPK[...,0:64] = K (stored at 64:) + P (stored in QP at 64:)
__global__ __launch_bounds__(256) void kp_add()
{
    size_t i = (size_t)blockIdx.x * 256 + threadIdx.x;  // over BH*SEQ*64
    size_t r = i >> 6, d = i & 63;
    g_KPK[r * 128 + d] = g_KPK[r * 128 + 64 + d] + g_QP[r * 128 + 64 + d];
}

// ---------------------------------------------------------------------------
// Scores: per (b,h), S[q,k] = (QP[q,:] . KPK[k,:]) * SCALE + mask[q,k]
// 2048x2048, K=128. Same 128x128x16 tiling. Writes raw (pre-softmax) scores.
// ---------------------------------------------------------------------------
__global__ __launch_bounds__(256) void gemm_scores(
    const float* __restrict__ mask, float* __restrict__ weights)
{
    const int bh = blockIdx.z;
    const float* A = g_QP  + (size_t)bh * SEQ * 128;
    const float* B = g_KPK + (size_t)bh * SEQ * 128;
    float* C = weights + (size_t)bh * SEQ * SEQ;

    __shared__ float As[16][128];
    __shared__ float Bs[16][128];
    const int tid = threadIdx.x;
    const int tx = tid & 15, ty = tid >> 4;
    const int m0 = blockIdx.y * 128, n0 = blockIdx.x * 128;

    float acc[8][8];
#pragma unroll
    for (int i = 0; i < 8; i++)
#pragma unroll
        for (int j = 0; j < 8; j++) acc[i][j] = 0.f;

    for (int kt = 0; kt < 128; kt += 16) {
#pragma unroll
        for (int l = 0; l < 2; l++) {
            int lin = tid + l * 256;
            int row = lin >> 2, c4 = lin & 3;
            float4 a = *(const float4*)(A + (size_t)(m0 + row) * 128 + kt + c4 * 4);
            As[c4 * 4 + 0][row] = a.x; As[c4 * 4 + 1][row] = a.y;
            As[c4 * 4 + 2][row] = a.z; As[c4 * 4 + 3][row] = a.w;
            float4 b = *(const float4*)(B + (size_t)(n0 + row) * 128 + kt + c4 * 4);
            Bs[c4 * 4 + 0][row] = b.x; Bs[c4 * 4 + 1][row] = b.y;
            Bs[c4 * 4 + 2][row] = b.z; Bs[c4 * 4 + 3][row] = b.w;
        }
        __syncthreads();
#pragma unroll
        for (int k = 0; k < 16; k++) {
            float a[8], b[8];
#pragma unroll
            for (int i = 0; i < 8; i++) a[i] = As[k][ty * 8 + i];
#pragma unroll
            for (int j = 0; j < 8; j++) b[j] = Bs[k][tx * 8 + j];
#pragma unroll
            for (int i = 0; i < 8; i++)
#pragma unroll
                for (int j = 0; j < 8; j++) acc[i][j] += a[i] * b[j];
        }
        __syncthreads();
    }

#pragma unroll
    for (int i = 0; i < 8; i++) {
        int q = m0 + ty * 8 + i;
#pragma unroll
        for (int j = 0; j < 8; j++) {
            int k = n0 + tx * 8 + j;
            C[(size_t)q * SEQ + k] = acc[i][j] * SCALE + mask[(size_t)q * SEQ + k];
        }
    }
}

// In-place row softmax over 2048 cols. One block (256 thr) per row.
__global__ __launch_bounds__(256) void softmax_rows(float* __restrict__ w)
{
    __shared__ float red[256];
    const size_t row = blockIdx.x;
    float* p = w + row * (size_t)SEQ;
    const int tid = threadIdx.x;

    float v[8];
    float mx = -1e30f;
#pragma unroll
    for (int i = 0; i < 8; i++) {
        v[i] = p[tid + i * 256];
        mx = fmaxf(mx, v[i]);
    }
    red[tid] = mx;
    __syncthreads();
    for (int s = 128; s > 0; s >>= 1) {
        if (tid < s) red[tid] = fmaxf(red[tid], red[tid + s]);
        __syncthreads();
    }
    mx = red[0];
    __syncthreads();

    float sum = 0.f;
#pragma unroll
    for (int i = 0; i < 8; i++) {
        v[i] = __expf(v[i] - mx);
        sum += v[i];
    }
    red[tid] = sum;
    __syncthreads();
    for (int s = 128; s > 0; s >>= 1) {
        if (tid < s) red[tid] += red[tid + s];
        __syncthreads();
    }
    float inv = 1.f / red[0];
#pragma unroll
    for (int i = 0; i < 8; i++) p[tid + i * 256] = v[i] * inv;
}

// ---------------------------------------------------------------------------
// AV: per (b,h), O[q,d] = sum_k W[q,k]*V[k,d].  M=2048, N=64, K=2048.
// BM=128, BN=64, BK=32. 256 threads, 8x4 per thread. O stored [b,s,h*64+d].
// ---------------------------------------------------------------------------
__global__ __launch_bounds__(256) void gemm_av(const float* __restrict__ weights)
{
    const int bh = blockIdx.y;
    const int b = bh >> 4, h = bh & 15;
    const float* Wm = weights + (size_t)bh * SEQ * SEQ;
    const float* V  = g_V + (size_t)bh * SEQ * HDIM;

    __shared__ float Ws[32][128];
    __shared__ float Vs[32][64];
    const int tid = threadIdx.x;
    const int tx = tid & 15, ty = tid >> 4;
    const int m0 = blockIdx.x * 128;

    float acc[8][4];
#pragma unroll
    for (int i = 0; i < 8; i++)
#pragma unroll
        for (int j = 0; j < 4; j++) acc[i][j] = 0.f;

    for (int kt = 0; kt < SEQ; kt += 32) {
#pragma unroll
        for (int l = 0; l < 4; l++) {
            int lin = tid + l * 256;             // [0,1024)
            int row = lin >> 3, c4 = lin & 7;
            float4 a = *(const float4*)(Wm + (size_t)(m0 + row) * SEQ + kt + c4 * 4);
            Ws[c4 * 4 + 0][row] = a.x; Ws[c4 * 4 + 1][row] = a.y;
            Ws[c4 * 4 + 2][row] = a.z; Ws[c4 * 4 + 3][row] = a.w;
        }
#pragma unroll
        for (int l = 0; l < 2; l++) {
            int lin = tid + l * 256;             // [0,512)
            int row = lin >> 4, c4 = lin & 15;
            *(float4*)&Vs[row][c4 * 4] =
                *(const float4*)(V + (size_t)(kt + row) * HDIM + c4 * 4);
        }
        __syncthreads();
#pragma unroll
        for (int k = 0; k < 32; k++) {
            float a[8], bb[4];
#pragma unroll
            for (int i = 0; i < 8; i++) a[i] = Ws[k][ty * 8 + i];
#pragma unroll
            for (int j = 0; j < 4; j++) bb[j] = Vs[k][tx * 4 + j];
#pragma unroll
            for (int i = 0; i < 8; i++)
#pragma unroll
                for (int j = 0; j < 4; j++) acc[i][j] += a[i] * bb[j];
        }
        __syncthreads();
    }

#pragma unroll
    for (int i = 0; i < 8; i++) {
        int s = m0 + ty * 8 + i;
#pragma unroll
        for (int j = 0; j < 4; j++) {
            int d = tx * 4 + j;
            g_O[(size_t)b * SEQ * HID + (size_t)s * HID + h * 64 + d] = acc[i][j];
        }
    }
}

// ---------------------------------------------------------------------------
extern "C" void kernel_launch(void* const* d_in, const int* in_sizes, int n_in,
                              void* d_out, int out_size)
{
    const float* q    = (const float*)d_in[0];
    const float* k    = (const float*)d_in[1];
    const float* v    = (const float*)d_in[2];
    const float* pos  = (const float*)d_in[3];
    const float* mask = (const float*)d_in[4];
    const float* Wq = (const float*)d_in[5];  const float* bq = (const float*)d_in[6];
    const float* Wk = (const float*)d_in[7];  const float* bk = (const float*)d_in[8];
    const float* Wv = (const float*)d_in[9];  const float* bv = (const float*)d_in[10];
    const float* Wp = (const float*)d_in[11]; const float* bp = (const float*)d_in[12];
    const float* Wo = (const float*)d_in[13]; const float* bo = (const float*)d_in[14];

    float* out = (float*)d_out;
    float* weights = out + (size_t)BATCH * SEQ * HID;   // out first, then weights

    float *QP, *KPK, *Vd, *O;
    cudaGetSymbolAddress((void**)&QP,  g_QP);
    cudaGetSymbolAddress((void**)&KPK, g_KPK);
    cudaGetSymbolAddress((void**)&Vd,  g_V);
    cudaGetSymbolAddress((void**)&O,   g_O);

    dim3 blk(256);
    dim3 gproj(HID / 128, M_TOTAL / 128);   // (8, 32)

    gemm_proj<<<gproj, blk>>>(q,   Wq, bq, QP,  1, 0);   // Q  -> QP[:,0:64]
    gemm_proj<<<gproj, blk>>>(pos, Wp, bp, QP,  1, 64);  // P  -> QP[:,64:128]
    gemm_proj<<<gproj, blk>>>(k,   Wk, bk, KPK, 1, 64);  // K  -> KPK[:,64:128]
    gemm_proj<<<gproj, blk>>>(v,   Wv, bv, Vd,  2, 0);   // V

    kp_add<<<(BH * SEQ * 64) / 256, blk>>>();            // KPK[:,0:64] = K + P

    dim3 gsc(SEQ / 128, SEQ / 128, BH);                  // (16,16,32)
    gemm_scores<<<gsc, blk>>>(mask, weights);

    softmax_rows<<<BH * SEQ, blk>>>(weights);

    gemm_av<<<dim3(SEQ / 128, BH), blk>>>(weights);

    gemm_proj<<<gproj, blk>>>(O, Wo, bo, out, 0, 0);     // final projection
}